// round 3
// baseline (speedup 1.0000x reference)
#include <cuda_runtime.h>
#include <cuda_bf16.h>

#define N_NODES 1000000
#define N_EDGES 32000000

// Scratch: per-node aggregation buffer (initialized to (1+eps)*x, then
// edge contributions are RED.ADD'ed in).
__device__ float g_agg[N_NODES];

// ---------------------------------------------------------------------------
// Kernel 1: agg[i] = (1 + eps) * x[i]   (fuses the self-term with the zeroing)
// ---------------------------------------------------------------------------
__global__ void init_agg_kernel(const float* __restrict__ x,
                                const float* __restrict__ eps) {
    const float e = 1.0f + *eps;   // scalar, L2-cached broadcast
    int idx = (blockIdx.x * blockDim.x + threadIdx.x) * 4;
    if (idx < N_NODES) {           // N_NODES % 4 == 0, float4 always in-bounds
        float4 v = *reinterpret_cast<const float4*>(x + idx);
        float4 r;
        r.x = e * v.x; r.y = e * v.y; r.z = e * v.z; r.w = e * v.w;
        *reinterpret_cast<float4*>(g_agg + idx) = r;
    }
}

// ---------------------------------------------------------------------------
// Kernel 2: for each edge (s, d): agg[d] += x[s]
// Indices are int32 (harness converts the reference's int64 to int32).
// 4 edges per thread: one int4 load of src indices, one int4 of dst indices.
// atomicAdd with discarded result -> RED.E.ADD.F32 (no return trip).
// ---------------------------------------------------------------------------
__global__ void edge_scatter_kernel(const int* __restrict__ src,
                                    const int* __restrict__ dst,
                                    const float* __restrict__ x) {
    long long t = blockIdx.x * (long long)blockDim.x + threadIdx.x;
    long long base = t * 4;   // exactly covers N_EDGES with the launch config

    int4 s = *reinterpret_cast<const int4*>(src + base);
    int4 d = *reinterpret_cast<const int4*>(dst + base);

    float v0 = __ldg(x + s.x);
    float v1 = __ldg(x + s.y);
    float v2 = __ldg(x + s.z);
    float v3 = __ldg(x + s.w);

    atomicAdd(&g_agg[d.x], v0);
    atomicAdd(&g_agg[d.y], v1);
    atomicAdd(&g_agg[d.z], v2);
    atomicAdd(&g_agg[d.w], v3);
}

// ---------------------------------------------------------------------------
// Kernel 3: out[i] = MLP(agg[i])   with MLP = L(1,20)->ReLU->L(20,20)->ReLU->L(20,1)
// Weights staged to shared memory; inner 20x20 fully unrolled.
// ---------------------------------------------------------------------------
__global__ void node_mlp_kernel(const float* __restrict__ w1,
                                const float* __restrict__ b1,
                                const float* __restrict__ w2,
                                const float* __restrict__ b2,
                                const float* __restrict__ w3,
                                const float* __restrict__ b3,
                                float* __restrict__ out) {
    __shared__ float sw1[20], sb1[20], sw2[400], sb2[20], sw3[20], sb3;
    int tid = threadIdx.x;
    if (tid < 20) {
        sw1[tid] = w1[tid];
        sb1[tid] = b1[tid];
        sb2[tid] = b2[tid];
        sw3[tid] = w3[tid];
    }
    for (int i = tid; i < 400; i += blockDim.x) sw2[i] = w2[i];
    if (tid == 0) sb3 = b3[0];
    __syncthreads();

    int i = blockIdx.x * blockDim.x + tid;
    if (i < N_NODES) {
        float s = g_agg[i];

        float h1[20];
        #pragma unroll
        for (int j = 0; j < 20; j++)
            h1[j] = fmaxf(fmaf(s, sw1[j], sb1[j]), 0.0f);

        float acc_out = sb3;
        #pragma unroll
        for (int k = 0; k < 20; k++) {
            float a = sb2[k];
            #pragma unroll
            for (int j = 0; j < 20; j++)
                a = fmaf(h1[j], sw2[j * 20 + k], a);
            acc_out = fmaf(fmaxf(a, 0.0f), sw3[k], acc_out);
        }
        out[i] = acc_out;
    }
}

// ---------------------------------------------------------------------------
// Launch. Inputs (metadata order):
//   0: x          [1M]  f32
//   1: edge_index [2, 32M] int32   (src = first 32M, dst = second 32M)
//   2: eps        [1]   f32
//   3: w1 [20]  4: b1 [20]  5: w2 [400]  6: b2 [20]  7: w3 [20]  8: b3 [1]
// Output: [1M] f32
// ---------------------------------------------------------------------------
extern "C" void kernel_launch(void* const* d_in, const int* in_sizes, int n_in,
                              void* d_out, int out_size) {
    const float* x   = (const float*)d_in[0];
    const int*   ei  = (const int*)d_in[1];
    const float* eps = (const float*)d_in[2];
    const float* w1  = (const float*)d_in[3];
    const float* b1  = (const float*)d_in[4];
    const float* w2  = (const float*)d_in[5];
    const float* b2  = (const float*)d_in[6];
    const float* w3  = (const float*)d_in[7];
    const float* b3  = (const float*)d_in[8];
    float* out = (float*)d_out;

    const int* src = ei;
    const int* dst = ei + N_EDGES;

    // 1) agg = (1+eps)*x : float4 per thread
    init_agg_kernel<<<(N_NODES / 4 + 255) / 256, 256>>>(x, eps);

    // 2) edge scatter: 8M threads, 4 edges each -> exactly 32M edges
    edge_scatter_kernel<<<N_EDGES / 4 / 256, 256>>>(src, dst, x);

    // 3) node MLP
    node_mlp_kernel<<<(N_NODES + 255) / 256, 256>>>(w1, b1, w2, b2, w3, b3, out);
}